// round 1
// baseline (speedup 1.0000x reference)
#include <cuda_runtime.h>

#define NGAUSS 2048
#define NCH    32
#define IMH    80
#define IMW    144
#define NVIEW  2
#define NEARP  0.2f
#define DILATE 0.3f
#define ALPHA_MIN (1.0f/255.0f)
#define T_EPS  1e-4f

// scratch: per-view unsorted attrs and depth-sorted attrs.
// layout per gaussian: f4[0] = {px, py, ca, cb}, f4[1] = {cc, op, tz, idx_bits}
__device__ float4 g_attr  [NVIEW][NGAUSS][2];
__device__ float4 g_sorted[NVIEW][NGAUSS][2];

// ---------------------------------------------------------------------------
// Phase 1+2: per-gaussian projection + conic, then stable bitonic depth sort.
// One CTA per view (1024 threads).
// ---------------------------------------------------------------------------
__global__ void prep_sort(const float* __restrict__ means,
                          const float* __restrict__ opac,
                          const float* __restrict__ scales,
                          const float* __restrict__ rots,
                          const float* __restrict__ cam2img,
                          const float* __restrict__ cam2ego)
{
    const int v   = blockIdx.x;
    const int tid = threadIdx.x;
    __shared__ unsigned long long keys[NGAUSS];

    const float* Km = cam2img + v * 9;
    const float* E  = cam2ego + v * 16;
    const float fx = Km[0], fy = Km[4], cx = Km[2], cy = Km[5];

    // R = cam2ego[:3,:3]^T ; T = -R @ cam2ego[:3,3]
    const float R00 = E[0], R01 = E[4], R02 = E[8];
    const float R10 = E[1], R11 = E[5], R12 = E[9];
    const float R20 = E[2], R21 = E[6], R22 = E[10];
    const float ex = E[3], ey = E[7], ez = E[11];
    const float Tx = -(R00*ex + R01*ey + R02*ez);
    const float Ty = -(R10*ex + R11*ey + R12*ez);
    const float Tz = -(R20*ex + R21*ey + R22*ez);
    const float tanfovx = (float)IMW * 0.5f / fx;
    const float tanfovy = (float)IMH * 0.5f / fy;

    for (int n = tid; n < NGAUSS; n += blockDim.x) {
        // quaternion -> rotation
        float qw = rots[n*4+0], qx = rots[n*4+1], qy = rots[n*4+2], qz = rots[n*4+3];
        float inv = rsqrtf(qw*qw + qx*qx + qy*qy + qz*qz);
        qw *= inv; qx *= inv; qy *= inv; qz *= inv;
        float r00 = 1.f - 2.f*(qy*qy + qz*qz), r01 = 2.f*(qx*qy - qw*qz), r02 = 2.f*(qx*qz + qw*qy);
        float r10 = 2.f*(qx*qy + qw*qz), r11 = 1.f - 2.f*(qx*qx + qz*qz), r12 = 2.f*(qy*qz - qw*qx);
        float r20 = 2.f*(qx*qz - qw*qy), r21 = 2.f*(qy*qz + qw*qx), r22 = 1.f - 2.f*(qx*qx + qy*qy);

        float sx = scales[n*3+0], sy = scales[n*3+1], sz = scales[n*3+2];
        float m00 = r00*sx, m01 = r01*sy, m02 = r02*sz;
        float m10 = r10*sx, m11 = r11*sy, m12 = r12*sz;
        float m20 = r20*sx, m21 = r21*sy, m22 = r22*sz;

        // Sigma = M M^T (symmetric)
        float S00 = m00*m00 + m01*m01 + m02*m02;
        float S01 = m00*m10 + m01*m11 + m02*m12;
        float S02 = m00*m20 + m01*m21 + m02*m22;
        float S11 = m10*m10 + m11*m11 + m12*m12;
        float S12 = m10*m20 + m11*m21 + m12*m22;
        float S22 = m20*m20 + m21*m21 + m22*m22;

        float mx = means[n*3+0], my = means[n*3+1], mz = means[n*3+2];
        float tx = R00*mx + R01*my + R02*mz + Tx;
        float ty = R10*mx + R11*my + R12*mz + Ty;
        float tz = R20*mx + R21*my + R22*mz + Tz;

        bool  valid = tz > NEARP;
        float tzs   = valid ? tz : 1.0f;
        float txtz  = fminf(fmaxf(tx/tzs, -1.3f*tanfovx), 1.3f*tanfovx);
        float tytz  = fminf(fmaxf(ty/tzs, -1.3f*tanfovy), 1.3f*tanfovy);

        // covcam = R Sigma R^T
        float A00 = R00*S00 + R01*S01 + R02*S02;
        float A01 = R00*S01 + R01*S11 + R02*S12;
        float A02 = R00*S02 + R01*S12 + R02*S22;
        float A10 = R10*S00 + R11*S01 + R12*S02;
        float A11 = R10*S01 + R11*S11 + R12*S12;
        float A12 = R10*S02 + R11*S12 + R12*S22;
        float A20 = R20*S00 + R21*S01 + R22*S02;
        float A21 = R20*S01 + R21*S11 + R22*S12;
        float A22 = R20*S02 + R21*S12 + R22*S22;
        float C00 = A00*R00 + A01*R01 + A02*R02;
        float C01 = A00*R10 + A01*R11 + A02*R12;
        float C02 = A00*R20 + A01*R21 + A02*R22;
        float C11 = A10*R10 + A11*R11 + A12*R12;
        float C12 = A10*R20 + A11*R21 + A12*R22;
        float C22 = A20*R20 + A21*R21 + A22*R22;

        // 2D cov = J C J^T with J = [[fx/tz, 0, -fx*txtz/tz],[0, fy/tz, -fy*tytz/tz]]
        float j00 = fx / tzs, j02 = -fx * txtz / tzs;
        float j11 = fy / tzs, j12 = -fy * tytz / tzs;
        float u0 = j00*C00 + j02*C02;
        float u1 = j00*C01 + j02*C12;
        float u2 = j00*C02 + j02*C22;
        float w1 = j11*C11 + j12*C12;
        float w2 = j11*C12 + j12*C22;
        float cov00 = u0*j00 + u2*j02;
        float cov01 = u1*j11 + u2*j12;
        float cov11 = w1*j11 + w2*j12;

        float a = cov00 + DILATE, b = cov01, c = cov11 + DILATE;
        float det = a*c - b*b;
        if (det == 0.f) det = 1.f;
        float ca = c / det, cb = -b / det, cc = a / det;

        float px = fx * tx / tzs + ((float)IMW - cx) - 0.5f;
        float py = fy * ty / tzs + ((float)IMH - cy) - 0.5f;
        float op = valid ? opac[n] : 0.f;

        g_attr[v][n][0] = make_float4(px, py, ca, cb);
        g_attr[v][n][1] = make_float4(cc, op, tz, __int_as_float(n));

        float keyf = valid ? tz : __int_as_float(0x7F800000);  // +inf
        keys[n] = (((unsigned long long)__float_as_uint(keyf)) << 32) | (unsigned)n;
    }
    __syncthreads();

    // bitonic sort, ascending; idx in low bits => stable (matches jnp.argsort)
    for (unsigned k = 2; k <= NGAUSS; k <<= 1) {
        for (unsigned j = k >> 1; j > 0; j >>= 1) {
            for (unsigned i = tid; i < NGAUSS; i += blockDim.x) {
                unsigned ixj = i ^ j;
                if (ixj > i) {
                    unsigned long long a0 = keys[i], b0 = keys[ixj];
                    bool up = ((i & k) == 0);
                    if ((a0 > b0) == up) { keys[i] = b0; keys[ixj] = a0; }
                }
            }
            __syncthreads();
        }
    }

    // gather into sorted, coalesced layout
    for (int i = tid; i < NGAUSS; i += blockDim.x) {
        unsigned idx = (unsigned)(keys[i] & 0xFFFFFFFFu);
        g_sorted[v][i][0] = g_attr[v][idx][0];
        g_sorted[v][i][1] = g_attr[v][idx][1];
    }
}

// ---------------------------------------------------------------------------
// Phase 3: tiled alpha-blend render. 8x8 pixel tiles, 64-gaussian SMEM batches.
// ---------------------------------------------------------------------------
__global__ void __launch_bounds__(64) render(const float* __restrict__ colors,
                                             float* __restrict__ out)
{
    const int v  = blockIdx.z;
    const int ix = blockIdx.x * 8 + threadIdx.x;
    const int iy = blockIdx.y * 8 + threadIdx.y;
    const int tid = threadIdx.y * 8 + threadIdx.x;
    const float X = (float)ix, Y = (float)iy;

    float acc[NCH];
#pragma unroll
    for (int c = 0; c < NCH; c++) acc[c] = 0.f;
    float dacc = 0.f;
    float T = 1.f;
    bool done = false;

    __shared__ float4 s0[64], s1[64];

    for (int base = 0; base < NGAUSS; base += 64) {
        s0[tid] = g_sorted[v][base + tid][0];
        s1[tid] = g_sorted[v][base + tid][1];
        __syncthreads();

        if (!done) {
            for (int j = 0; j < 64; j++) {
                float4 A = s0[j];
                float4 B = s1[j];
                float dx = X - A.x, dy = Y - A.y;
                float power = -0.5f * (A.z * dx * dx + B.x * dy * dy) - A.w * dx * dy;
                float al = fminf(0.99f, B.y * __expf(power));
                // NaN-safe skip: invalid gaussians have op=0 (al=0 or NaN)
                if (power > 0.f || !(al >= ALPHA_MIN)) continue;
                float Tn = T * (1.f - al);
                if (Tn >= T_EPS) {
                    float w = al * T;
                    const float4* crow =
                        (const float4*)(colors + (size_t)((unsigned)__float_as_int(B.w)) * NCH);
#pragma unroll
                    for (int c4 = 0; c4 < 8; c4++) {
                        float4 cv = crow[c4];
                        acc[c4*4+0] += w * cv.x;
                        acc[c4*4+1] += w * cv.y;
                        acc[c4*4+2] += w * cv.z;
                        acc[c4*4+3] += w * cv.w;
                    }
                    dacc += w * B.z;
                }
                T = Tn;
                if (T < T_EPS) { done = true; break; }  // all later weights are 0
            }
        }
        if (__syncthreads_and(done)) break;  // barrier also protects smem reuse
    }

#pragma unroll
    for (int c = 0; c < NCH; c++)
        out[((size_t)(v * NCH + c) * IMH + iy) * IMW + ix] = acc[c];
    out[(size_t)NVIEW * NCH * IMH * IMW + (size_t)(v * IMH + iy) * IMW + ix] = dacc;
}

// ---------------------------------------------------------------------------
extern "C" void kernel_launch(void* const* d_in, const int* in_sizes, int n_in,
                              void* d_out, int out_size)
{
    const float* means   = (const float*)d_in[0];
    const float* colors  = (const float*)d_in[1];
    const float* opac    = (const float*)d_in[2];
    const float* scales  = (const float*)d_in[3];
    const float* rots    = (const float*)d_in[4];
    const float* cam2img = (const float*)d_in[5];
    const float* cam2ego = (const float*)d_in[6];
    float* out = (float*)d_out;

    prep_sort<<<NVIEW, 1024>>>(means, opac, scales, rots, cam2img, cam2ego);
    render<<<dim3(IMW/8, IMH/8, NVIEW), dim3(8, 8)>>>(colors, out);
}

// round 2
// speedup vs baseline: 3.7577x; 3.7577x over previous
#include <cuda_runtime.h>

#define NGAUSS 2048
#define NCH    32
#define IMH    80
#define IMW    144
#define NVIEW  2
#define NEARP  0.2f
#define DILATE 0.3f
#define ALPHA_MIN (1.0f/255.0f)
#define T_EPS  1e-4f
#define BATCH  256   // gaussians culled per cooperative round (4 sub-chunks of 64)

// unsorted per-gaussian attrs: [0]={px,py,ca,cb} [1]={cc,op,tz,idx} ; cull={px,py,rx,ry}
__device__ float4 g_attr  [NVIEW][NGAUSS][2];
__device__ float4 g_cullu [NVIEW][NGAUSS];
// depth-sorted copies
__device__ float4 g_sorted[NVIEW][NGAUSS][2];
__device__ float4 g_cull  [NVIEW][NGAUSS];

// ---------------------------------------------------------------------------
// Phase 1+2: projection + conic + bbox radii, then stable bitonic depth sort.
// One CTA per view, 1024 threads.
// ---------------------------------------------------------------------------
__global__ void prep_sort(const float* __restrict__ means,
                          const float* __restrict__ opac,
                          const float* __restrict__ scales,
                          const float* __restrict__ rots,
                          const float* __restrict__ cam2img,
                          const float* __restrict__ cam2ego)
{
    const int v   = blockIdx.x;
    const int tid = threadIdx.x;
    __shared__ unsigned long long keys[NGAUSS];

    const float* Km = cam2img + v * 9;
    const float* E  = cam2ego + v * 16;
    const float fx = Km[0], fy = Km[4], cx = Km[2], cy = Km[5];

    const float R00 = E[0], R01 = E[4], R02 = E[8];
    const float R10 = E[1], R11 = E[5], R12 = E[9];
    const float R20 = E[2], R21 = E[6], R22 = E[10];
    const float ex = E[3], ey = E[7], ez = E[11];
    const float Tx = -(R00*ex + R01*ey + R02*ez);
    const float Ty = -(R10*ex + R11*ey + R12*ez);
    const float Tz = -(R20*ex + R21*ey + R22*ez);
    const float tanfovx = (float)IMW * 0.5f / fx;
    const float tanfovy = (float)IMH * 0.5f / fy;

    for (int n = tid; n < NGAUSS; n += blockDim.x) {
        float qw = rots[n*4+0], qx = rots[n*4+1], qy = rots[n*4+2], qz = rots[n*4+3];
        float inv = rsqrtf(qw*qw + qx*qx + qy*qy + qz*qz);
        qw *= inv; qx *= inv; qy *= inv; qz *= inv;
        float r00 = 1.f - 2.f*(qy*qy + qz*qz), r01 = 2.f*(qx*qy - qw*qz), r02 = 2.f*(qx*qz + qw*qy);
        float r10 = 2.f*(qx*qy + qw*qz), r11 = 1.f - 2.f*(qx*qx + qz*qz), r12 = 2.f*(qy*qz - qw*qx);
        float r20 = 2.f*(qx*qz - qw*qy), r21 = 2.f*(qy*qz + qw*qx), r22 = 1.f - 2.f*(qx*qx + qy*qy);

        float sx = scales[n*3+0], sy = scales[n*3+1], sz = scales[n*3+2];
        float m00 = r00*sx, m01 = r01*sy, m02 = r02*sz;
        float m10 = r10*sx, m11 = r11*sy, m12 = r12*sz;
        float m20 = r20*sx, m21 = r21*sy, m22 = r22*sz;

        float S00 = m00*m00 + m01*m01 + m02*m02;
        float S01 = m00*m10 + m01*m11 + m02*m12;
        float S02 = m00*m20 + m01*m21 + m02*m22;
        float S11 = m10*m10 + m11*m11 + m12*m12;
        float S12 = m10*m20 + m11*m21 + m12*m22;
        float S22 = m20*m20 + m21*m21 + m22*m22;

        float mx = means[n*3+0], my = means[n*3+1], mz = means[n*3+2];
        float tx = R00*mx + R01*my + R02*mz + Tx;
        float ty = R10*mx + R11*my + R12*mz + Ty;
        float tz = R20*mx + R21*my + R22*mz + Tz;

        bool  valid = tz > NEARP;
        float tzs   = valid ? tz : 1.0f;
        float txtz  = fminf(fmaxf(tx/tzs, -1.3f*tanfovx), 1.3f*tanfovx);
        float tytz  = fminf(fmaxf(ty/tzs, -1.3f*tanfovy), 1.3f*tanfovy);

        float A00 = R00*S00 + R01*S01 + R02*S02;
        float A01 = R00*S01 + R01*S11 + R02*S12;
        float A02 = R00*S02 + R01*S12 + R02*S22;
        float A10 = R10*S00 + R11*S01 + R12*S02;
        float A11 = R10*S01 + R11*S11 + R12*S12;
        float A12 = R10*S02 + R11*S12 + R12*S22;
        float A20 = R20*S00 + R21*S01 + R22*S02;
        float A21 = R20*S01 + R21*S11 + R22*S12;
        float A22 = R20*S02 + R21*S12 + R22*S22;
        float C00 = A00*R00 + A01*R01 + A02*R02;
        float C01 = A00*R10 + A01*R11 + A02*R12;
        float C02 = A00*R20 + A01*R21 + A02*R22;
        float C11 = A10*R10 + A11*R11 + A12*R12;
        float C12 = A10*R20 + A11*R21 + A12*R22;
        float C22 = A20*R20 + A21*R21 + A22*R22;

        float j00 = fx / tzs, j02 = -fx * txtz / tzs;
        float j11 = fy / tzs, j12 = -fy * tytz / tzs;
        float u0 = j00*C00 + j02*C02;
        float u1 = j00*C01 + j02*C12;
        float u2 = j00*C02 + j02*C22;
        float w1 = j11*C11 + j12*C12;
        float w2 = j11*C12 + j12*C22;
        float cov00 = u0*j00 + u2*j02;
        float cov01 = u1*j11 + u2*j12;
        float cov11 = w1*j11 + w2*j12;

        float a = cov00 + DILATE, b = cov01, c = cov11 + DILATE;
        float det = a*c - b*b;
        if (det == 0.f) det = 1.f;
        float ca = c / det, cb = -b / det, cc = a / det;

        float px = fx * tx / tzs + ((float)IMW - cx) - 0.5f;
        float py = fy * ty / tzs + ((float)IMH - cy) - 0.5f;
        float op = valid ? opac[n] : 0.f;

        // bbox radii of the alpha >= 1/255 level set: Q <= t, t = ln(255*op)
        // op<=1/255 or op==0 -> t<=0 or NaN -> rx/ry NaN -> all bbox compares false -> culled
        float t  = __logf(255.f * op);
        float rx = sqrtf(2.f * t * a) * 1.0001f + 1e-3f;
        float ry = sqrtf(2.f * t * c) * 1.0001f + 1e-3f;

        g_attr [v][n][0] = make_float4(px, py, ca, cb);
        g_attr [v][n][1] = make_float4(cc, op, tz, __int_as_float(n));
        g_cullu[v][n]    = make_float4(px, py, rx, ry);

        float keyf = valid ? tz : __int_as_float(0x7F800000);  // +inf
        keys[n] = (((unsigned long long)__float_as_uint(keyf)) << 32) | (unsigned)n;
    }
    __syncthreads();

    // bitonic sort, ascending, 1024 threads = exactly NGAUSS/2 compare-exchanges/step
    for (unsigned k = 2; k <= NGAUSS; k <<= 1) {
        for (unsigned j = k >> 1; j > 0; j >>= 1) {
            unsigned t = tid;
            unsigned i   = ((t & ~(j - 1u)) << 1) | (t & (j - 1u));
            unsigned ixj = i | j;
            unsigned long long a0 = keys[i], b0 = keys[ixj];
            bool up = ((i & k) == 0);
            if ((a0 > b0) == up) { keys[i] = b0; keys[ixj] = a0; }
            __syncthreads();
        }
    }

    for (int i = tid; i < NGAUSS; i += blockDim.x) {
        unsigned idx = (unsigned)(keys[i] & 0xFFFFFFFFu);
        g_sorted[v][i][0] = g_attr [v][idx][0];
        g_sorted[v][i][1] = g_attr [v][idx][1];
        g_cull  [v][i]    = g_cullu[v][idx];
    }
}

// ---------------------------------------------------------------------------
// Phase 3: tiled render with fused depth-ordered tile culling.
// 8x8 pixel tiles, 64 threads; BATCH=256 gaussians culled per round.
// ---------------------------------------------------------------------------
__global__ void __launch_bounds__(64) render(const float* __restrict__ colors,
                                             float* __restrict__ out)
{
    const int v   = blockIdx.z;
    const int ix  = blockIdx.x * 8 + threadIdx.x;
    const int iy  = blockIdx.y * 8 + threadIdx.y;
    const int tid = threadIdx.y * 8 + threadIdx.x;
    const int wid = tid >> 5, lane = tid & 31;
    const float X = (float)ix, Y = (float)iy;

    const float xmin = (float)(blockIdx.x * 8);
    const float xmax = xmin + 7.0f;
    const float ymin = (float)(blockIdx.y * 8);
    const float ymax = ymin + 7.0f;

    float acc[NCH];
#pragma unroll
    for (int c = 0; c < NCH; c++) acc[c] = 0.f;
    float dacc = 0.f;
    float T = 1.f;
    bool done = false;

    __shared__ float4 s0[BATCH], s1[BATCH];
    __shared__ unsigned sball[8];   // [chunk*2 + warp], depth order

    for (int base = 0; base < NGAUSS; base += BATCH) {
        bool hit[4];
        unsigned myb[4];
#pragma unroll
        for (int k = 0; k < 4; k++) {
            float4 cd = g_cull[v][base + k * 64 + tid];
            // NaN-safe: any NaN -> false -> culled
            hit[k] = (cd.x - cd.z <= xmax) && (cd.x + cd.z >= xmin) &&
                     (cd.y - cd.w <= ymax) && (cd.y + cd.w >= ymin);
            myb[k] = __ballot_sync(0xffffffffu, hit[k]);
        }
        if (lane == 0) {
#pragma unroll
            for (int k = 0; k < 4; k++) sball[k * 2 + wid] = myb[k];
        }
        __syncthreads();   // ballots visible; also fences prior round's s0/s1 reads

        unsigned bl[8];
        int total = 0;
#pragma unroll
        for (int i = 0; i < 8; i++) { bl[i] = sball[i]; total += __popc(bl[i]); }

#pragma unroll
        for (int k = 0; k < 4; k++) {
            if (hit[k]) {
                int ord = k * 2 + wid;
                int off = 0;
                for (int i = 0; i < ord; i++) off += __popc(bl[i]);
                off += __popc(myb[k] & ((1u << lane) - 1u));
                int g = base + k * 64 + tid;
                s0[off] = g_sorted[v][g][0];
                s1[off] = g_sorted[v][g][1];
            }
        }
        __syncthreads();

        if (!done) {
            for (int j = 0; j < total; j++) {
                float4 A = s0[j];
                float4 B = s1[j];
                float dx = X - A.x, dy = Y - A.y;
                float power = -0.5f * (A.z * dx * dx + B.x * dy * dy) - A.w * dx * dy;
                float al = fminf(0.99f, B.y * __expf(power));
                if (power > 0.f || !(al >= ALPHA_MIN)) continue;
                float Tn = T * (1.f - al);
                if (Tn >= T_EPS) {
                    float w = al * T;
                    const float4* crow =
                        (const float4*)(colors + (size_t)((unsigned)__float_as_int(B.w)) * NCH);
#pragma unroll
                    for (int c4 = 0; c4 < 8; c4++) {
                        float4 cv = crow[c4];
                        acc[c4*4+0] += w * cv.x;
                        acc[c4*4+1] += w * cv.y;
                        acc[c4*4+2] += w * cv.z;
                        acc[c4*4+3] += w * cv.w;
                    }
                    dacc += w * B.z;
                }
                T = Tn;
                if (T < T_EPS) { done = true; break; }
            }
        }
        if (__syncthreads_and(done)) break;
    }

#pragma unroll
    for (int c = 0; c < NCH; c++)
        out[((size_t)(v * NCH + c) * IMH + iy) * IMW + ix] = acc[c];
    out[(size_t)NVIEW * NCH * IMH * IMW + (size_t)(v * IMH + iy) * IMW + ix] = dacc;
}

// ---------------------------------------------------------------------------
extern "C" void kernel_launch(void* const* d_in, const int* in_sizes, int n_in,
                              void* d_out, int out_size)
{
    const float* means   = (const float*)d_in[0];
    const float* colors  = (const float*)d_in[1];
    const float* opac    = (const float*)d_in[2];
    const float* scales  = (const float*)d_in[3];
    const float* rots    = (const float*)d_in[4];
    const float* cam2img = (const float*)d_in[5];
    const float* cam2ego = (const float*)d_in[6];
    float* out = (float*)d_out;

    prep_sort<<<NVIEW, 1024>>>(means, opac, scales, rots, cam2img, cam2ego);
    render<<<dim3(IMW/8, IMH/8, NVIEW), dim3(8, 8)>>>(colors, out);
}